// round 2
// baseline (speedup 1.0000x reference)
#include <cuda_runtime.h>
#include <cstdint>

// Dilution 2x: x [8,3,512,512] f32 -> out [8,3,1024,1024] f32
// out[b,c,2y,2x] = x[b,c,y,x]; all other outputs 0.
//
// One warp == one output row (1024 floats = 256 float4).
// Each thread handles 8 float4s strided by 32, so every store instruction is
// warp-coalesced over a contiguous 512 B span. Output float4 index o within the
// row covers cols [4o,4o+4) and needs input float2 index o of the input row.
// Even rows: 8 independent float2 loads batched first (MLP=8), then 8 stores.
// Odd rows: 8 pure zero stores, no loads (warp-uniform branch).

static constexpr int HF = 512, WF = 512;
static constexpr int HT = 1024, WT = 1024;
static constexpr int PLANES = 8 * 3;
static constexpr int F4_PER_ROW = WT / 4;                  // 256
static constexpr int THREADS_PER_ROW = 32;                 // one warp per row
static constexpr int TOTAL_THREADS = PLANES * HT * THREADS_PER_ROW;  // 786,432
static constexpr int BLOCK = 256;

__global__ void __launch_bounds__(BLOCK)
dilution_kernel(const float* __restrict__ in, float4* __restrict__ out) {
    unsigned idx   = blockIdx.x * BLOCK + threadIdx.x;
    unsigned t     = idx & 31u;                 // lane within row
    unsigned row   = (idx >> 5) & (HT - 1u);    // output row
    unsigned plane = idx >> 15;                 // b*C + c

    float4* orow = out + (size_t)(plane * HT + row) * F4_PER_ROW;

    if (row & 1u) {
        const float4 z = make_float4(0.f, 0.f, 0.f, 0.f);
        #pragma unroll
        for (int i = 0; i < 8; i++)
            orow[i * 32 + t] = z;
    } else {
        const float2* irow = reinterpret_cast<const float2*>(
            in + (size_t)(plane * HF + (row >> 1)) * WF);
        float2 a[8];
        #pragma unroll
        for (int i = 0; i < 8; i++)             // 8 independent loads up front
            a[i] = __ldg(&irow[i * 32 + t]);
        #pragma unroll
        for (int i = 0; i < 8; i++)
            orow[i * 32 + t] = make_float4(a[i].x, 0.f, a[i].y, 0.f);
    }
}

extern "C" void kernel_launch(void* const* d_in, const int* in_sizes, int n_in,
                              void* d_out, int out_size) {
    (void)in_sizes; (void)n_in; (void)out_size;
    const float* x = (const float*)d_in[0];
    float4* out = (float4*)d_out;
    dilution_kernel<<<TOTAL_THREADS / BLOCK, BLOCK>>>(x, out);
}

// round 5
// speedup vs baseline: 1.0026x; 1.0026x over previous
#include <cuda_runtime.h>
#include <cstdint>

// Dilution 2x: x [8,3,512,512] f32 -> out [8,3,1024,1024] f32
// out[b,c,2y,2x] = x[b,c,y,x]; all other outputs 0.
//
// R2 established: bound by L2 (LTS) throughput with ~69MB/replay avoidable DRAM
// victim/fill traffic (126MB working set thrashes L2 under LRU).
// R5: pin output in L2 (st.global.L2::evict_last), stream input
// (ld.global.nc.L2::evict_first). sm_100 ptxas requires these hints on 256-bit
// accesses only (.v8.b32), so everything is 32B chunks:
//   - output row = 128 chunks (4KB), input row = 64 chunks (2KB)
//   - one warp per output row
//   - even rows: 2 v8 loads/thread (input chunks i*32+t), then for each loaded
//     chunk c emit output chunks 2c and 2c+1 (a0,0,a1,0,... / a4,0,a5,0,...)
//   - odd rows: 4 contiguous v8 zero stores, no loads

static constexpr int HF = 512, WF = 512;
static constexpr int HT = 1024, WT = 1024;
static constexpr int PLANES = 8 * 3;
static constexpr int OCH_PER_ROW = WT * 4 / 32;        // 128 output 32B chunks/row
static constexpr int ICH_PER_ROW = WF * 4 / 32;        // 64 input 32B chunks/row
static constexpr int TOTAL_THREADS = PLANES * HT * 32; // warp per row = 786,432
static constexpr int BLOCK = 256;

struct V8 { uint32_t r[8]; };

__device__ __forceinline__ V8 ldg_ef8(const uint32_t* p) {
    V8 v;
    asm("ld.global.nc.L2::evict_first.v8.b32 {%0,%1,%2,%3,%4,%5,%6,%7}, [%8];"
        : "=r"(v.r[0]), "=r"(v.r[1]), "=r"(v.r[2]), "=r"(v.r[3]),
          "=r"(v.r[4]), "=r"(v.r[5]), "=r"(v.r[6]), "=r"(v.r[7])
        : "l"(p));
    return v;
}

__device__ __forceinline__ void stg_el8(uint32_t* p,
                                        uint32_t a, uint32_t b, uint32_t c, uint32_t d,
                                        uint32_t e, uint32_t f, uint32_t g, uint32_t h) {
    asm volatile("st.global.L2::evict_last.v8.b32 [%0], {%1,%2,%3,%4,%5,%6,%7,%8};"
                 :: "l"(p), "r"(a), "r"(b), "r"(c), "r"(d),
                    "r"(e), "r"(f), "r"(g), "r"(h) : "memory");
}

__global__ void __launch_bounds__(BLOCK)
dilution_kernel(const uint32_t* __restrict__ in, uint32_t* __restrict__ out) {
    unsigned idx   = blockIdx.x * BLOCK + threadIdx.x;
    unsigned t     = idx & 31u;                 // lane
    unsigned row   = (idx >> 5) & (HT - 1u);    // output row
    unsigned plane = idx >> 15;                 // b*C + c

    uint32_t* orow = out + (size_t)(plane * HT + row) * WT;  // in 4B words

    if (row & 1u) {
        #pragma unroll
        for (int i = 0; i < 4; i++) {
            unsigned ch = i * 32 + t;           // contiguous per instruction
            stg_el8(orow + ch * 8, 0u, 0u, 0u, 0u, 0u, 0u, 0u, 0u);
        }
    } else {
        const uint32_t* irow = in + (size_t)(plane * HF + (row >> 1)) * WF;
        V8 a[2];
        #pragma unroll
        for (int i = 0; i < 2; i++)             // independent loads up front
            a[i] = ldg_ef8(irow + (i * 32 + t) * 8);
        #pragma unroll
        for (int i = 0; i < 2; i++) {
            unsigned c = i * 32 + t;            // loaded input chunk index
            uint32_t* p = orow + c * 16;        // output chunk 2c (floats 16c..)
            stg_el8(p,      a[i].r[0], 0u, a[i].r[1], 0u, a[i].r[2], 0u, a[i].r[3], 0u);
            stg_el8(p + 8,  a[i].r[4], 0u, a[i].r[5], 0u, a[i].r[6], 0u, a[i].r[7], 0u);
        }
    }
}

extern "C" void kernel_launch(void* const* d_in, const int* in_sizes, int n_in,
                              void* d_out, int out_size) {
    (void)in_sizes; (void)n_in; (void)out_size;
    const uint32_t* x = (const uint32_t*)d_in[0];
    uint32_t* out = (uint32_t*)d_out;
    dilution_kernel<<<TOTAL_THREADS / BLOCK, BLOCK>>>(x, out);
}

// round 6
// speedup vs baseline: 1.1372x; 1.1342x over previous
#include <cuda_runtime.h>
#include <cstdint>

// Dilution 2x: x [8,3,512,512] f32 -> out [8,3,1024,1024] f32
// out[b,c,2y,2x] = x[b,c,y,x]; all other outputs 0.
//
// R5 finding: uniform evict_last failed to pin (resident set 125MB ~= L2 cap);
// kernel is LTS-traffic bound (~10.2 TB/s delivered at the practical cap).
// R6: split cache policy so the resident set (75MB) actually fits:
//   even rows (data, 50MB):  st evict_last -> pinned, re-dirtied in place
//   input (25MB):            ld evict_last -> pinned after first replay
//   odd rows (zeros, 50MB):  st evict_first -> streamed to DRAM, no pollution
// All accesses 256-bit (sm_100 requires v8.b32 for L2::evict_* hints).
//
// Layout: one warp per output row. Even rows: 2 v8 loads/thread then 4 v8
// stores interleaving zeros; odd rows: 4 contiguous v8 zero stores, no loads.

static constexpr int HF = 512, WF = 512;
static constexpr int HT = 1024, WT = 1024;
static constexpr int PLANES = 8 * 3;
static constexpr int TOTAL_THREADS = PLANES * HT * 32; // warp per row = 786,432
static constexpr int BLOCK = 256;

struct V8 { uint32_t r[8]; };

__device__ __forceinline__ V8 ldg_el8(const uint32_t* p) {
    V8 v;
    asm("ld.global.nc.L2::evict_last.v8.b32 {%0,%1,%2,%3,%4,%5,%6,%7}, [%8];"
        : "=r"(v.r[0]), "=r"(v.r[1]), "=r"(v.r[2]), "=r"(v.r[3]),
          "=r"(v.r[4]), "=r"(v.r[5]), "=r"(v.r[6]), "=r"(v.r[7])
        : "l"(p));
    return v;
}

__device__ __forceinline__ void stg_el8(uint32_t* p,
                                        uint32_t a, uint32_t b, uint32_t c, uint32_t d,
                                        uint32_t e, uint32_t f, uint32_t g, uint32_t h) {
    asm volatile("st.global.L2::evict_last.v8.b32 [%0], {%1,%2,%3,%4,%5,%6,%7,%8};"
                 :: "l"(p), "r"(a), "r"(b), "r"(c), "r"(d),
                    "r"(e), "r"(f), "r"(g), "r"(h) : "memory");
}

__device__ __forceinline__ void stg_ef8_zero(uint32_t* p) {
    asm volatile("st.global.L2::evict_first.v8.b32 [%0], {%1,%1,%1,%1,%1,%1,%1,%1};"
                 :: "l"(p), "r"(0u) : "memory");
}

__global__ void __launch_bounds__(BLOCK)
dilution_kernel(const uint32_t* __restrict__ in, uint32_t* __restrict__ out) {
    unsigned idx   = blockIdx.x * BLOCK + threadIdx.x;
    unsigned t     = idx & 31u;                 // lane
    unsigned row   = (idx >> 5) & (HT - 1u);    // output row
    unsigned plane = idx >> 15;                 // b*C + c

    uint32_t* orow = out + (size_t)(plane * HT + row) * WT;  // in 4B words

    if (row & 1u) {
        // zero rows: streamed, contiguous per instruction
        #pragma unroll
        for (int i = 0; i < 4; i++)
            stg_ef8_zero(orow + (i * 32 + t) * 8);
    } else {
        const uint32_t* irow = in + (size_t)(plane * HF + (row >> 1)) * WF;
        V8 a[2];
        #pragma unroll
        for (int i = 0; i < 2; i++)             // independent loads up front
            a[i] = ldg_el8(irow + (i * 32 + t) * 8);
        #pragma unroll
        for (int i = 0; i < 2; i++) {
            unsigned c = i * 32 + t;            // loaded input chunk index
            uint32_t* p = orow + c * 16;        // output chunk 2c
            stg_el8(p,      a[i].r[0], 0u, a[i].r[1], 0u, a[i].r[2], 0u, a[i].r[3], 0u);
            stg_el8(p + 8,  a[i].r[4], 0u, a[i].r[5], 0u, a[i].r[6], 0u, a[i].r[7], 0u);
        }
    }
}

extern "C" void kernel_launch(void* const* d_in, const int* in_sizes, int n_in,
                              void* d_out, int out_size) {
    (void)in_sizes; (void)n_in; (void)out_size;
    const uint32_t* x = (const uint32_t*)d_in[0];
    uint32_t* out = (uint32_t*)d_out;
    dilution_kernel<<<TOTAL_THREADS / BLOCK, BLOCK>>>(x, out);
}